// round 9
// baseline (speedup 1.0000x reference)
#include <cuda_runtime.h>
#include <cuda_fp16.h>
#include <cstdint>

// Problem constants
#define PIX    40000
#define PIXP   40064        // 313 * 128
#define CIN    256
#define RDIM   1024
#define NNODE  300
#define NTILE  128          // nodes per mask-GEMM tile
#define MAXT   6
#define NSLOT  (MAXT * NTILE)   // 768
#define KS     10
#define PCHUNK (PIX / KS)   // 4000
#define LDK    40           // smem k-pitch (fp16): 80B rows, 16B aligned

typedef __half fp16;

// Scratch (device globals — no allocation allowed)
__device__ fp16  g_H[(size_t)3 * RDIM * PIXP];          // H^T per branch [r][p], 246MB
__device__ fp16  g_xh[(size_t)PIXP * CIN];              // x transposed, fp16
__device__ fp16  g_w1[(size_t)3 * RDIM * CIN];          // W1^T fp16 [branch][r][c]
__device__ fp16  g_mTbf[(size_t)NSLOT * PIXP];          // masks transposed [slot][p]
__device__ float g_Spart[(size_t)KS * NNODE * RDIM];
__device__ float g_S[(size_t)NNODE * RDIM];
__device__ int   g_counts[NNODE];
__device__ int   g_order[NSLOT];
__device__ int   g_tileLabel[MAXT];
__device__ int   g_maskMode;                            // 0=u8, 1=i32, 2=f32
__device__ int   g_usedSlots;                           // ntiles*NTILE actually used

// ---------------------------------------------------------------------------
__device__ __forceinline__ void mma16816(float* c, uint32_t a0, uint32_t a1,
                                         uint32_t a2, uint32_t a3,
                                         uint32_t b0, uint32_t b1) {
    asm volatile(
        "mma.sync.aligned.m16n8k16.row.col.f32.f16.f16.f32 "
        "{%0,%1,%2,%3},{%4,%5,%6,%7},{%8,%9},{%0,%1,%2,%3};"
        : "+f"(c[0]), "+f"(c[1]), "+f"(c[2]), "+f"(c[3])
        : "r"(a0), "r"(a1), "r"(a2), "r"(a3), "r"(b0), "r"(b1));
}
__device__ __forceinline__ uint32_t s2u(const void* p) {
    return (uint32_t)__cvta_generic_to_shared(p);
}
__device__ __forceinline__ void ldsm4(uint32_t* r, uint32_t a) {
    asm volatile("ldmatrix.sync.aligned.m8n8.x4.shared.b16 {%0,%1,%2,%3},[%4];"
                 : "=r"(r[0]), "=r"(r[1]), "=r"(r[2]), "=r"(r[3]) : "r"(a));
}
#define CP16(dst, src) asm volatile("cp.async.cg.shared.global [%0],[%1],16;\n" :: "r"(dst), "l"(src))
#define CPCOMMIT() asm volatile("cp.async.commit_group;\n" ::)
#define CPWAIT1() asm volatile("cp.async.wait_group 1;\n" ::)
#define CPWAIT0() asm volatile("cp.async.wait_group 0;\n" ::)

// ---------------------------------------------------------------------------
// K0: detect mask dtype; bucket nodes by label into 128-padded tiles; zero counts.
// ---------------------------------------------------------------------------
__global__ void k_prep(const int* __restrict__ labels, const void* __restrict__ masks_raw) {
    if (threadIdx.x != 0) return;
    const unsigned int* w = (const unsigned int*)masks_raw;
    bool sawFloat = false, sawGT1 = false;
    for (int i = 0; i < 4096; i++) {
        unsigned int v = w[i];
        if (v == 0x3F800000u) sawFloat = true;
        else if (v > 1u) sawGT1 = true;
    }
    g_maskMode = sawFloat ? 2 : (sawGT1 ? 0 : 1);

    for (int i = 0; i < NNODE; i++) g_counts[i] = 0;
    int pos = 0, tile = 0;
    for (int lab = 0; lab < 3; lab++) {
        int start = pos;
        for (int n = 0; n < NNODE; n++)
            if (labels[n] == lab) g_order[pos++] = n;
        if (pos > start) {
            while ((pos - start) % NTILE) g_order[pos++] = -1;
            for (int t = start; t < pos; t += NTILE) g_tileLabel[tile++] = lab;
        }
    }
    g_usedSlots = pos;
    while (pos < NSLOT) g_order[pos++] = -1;
    for (; tile < MAXT; tile++) g_tileLabel[tile] = -1;
}

// ---------------------------------------------------------------------------
// K1 (fused): per 128-pixel block — raw masks -> smem, counts, transposed fp16.
// ---------------------------------------------------------------------------
__global__ __launch_bounds__(256) void k_maskfuse(const void* __restrict__ masks_raw) {
    __shared__ unsigned char m8[128 * NNODE];
    __shared__ int s_order[NSLOT];

    int tid = threadIdx.x;
    int p0 = blockIdx.x * 128;
    int rows = PIX - p0; if (rows > 128) rows = 128;
    int mode = g_maskMode;
    int used = g_usedSlots;

    for (int i = tid; i < NSLOT; i += 256) s_order[i] = g_order[i];

    int total = rows * NNODE;
    if (mode == 0) {
        const unsigned int* src = (const unsigned int*)masks_raw + (size_t)p0 * NNODE / 4;
        unsigned int* dst = (unsigned int*)m8;
        for (int i = tid; i < total / 4; i += 256) dst[i] = src[i];
        for (int i = total & ~3; i < total; i++) if (tid == 0) m8[i] = ((const unsigned char*)masks_raw)[(size_t)p0 * NNODE + i];
    } else if (mode == 1) {
        const int* src = (const int*)masks_raw + (size_t)p0 * NNODE;
        for (int i = tid; i < total; i += 256) m8[i] = (unsigned char)(src[i] != 0);
    } else {
        const float* src = (const float*)masks_raw + (size_t)p0 * NNODE;
        for (int i = tid; i < total; i += 256) m8[i] = (unsigned char)(src[i] != 0.0f);
    }
    __syncthreads();

    for (int n = tid; n < NNODE; n += 256) {
        int c = 0;
        for (int pl = 0; pl < rows; pl++) c += m8[pl * NNODE + n];
        atomicAdd(&g_counts[n], c);
    }

    int lim = ((used + NTILE - 1) / NTILE) * NTILE * 128;   // whole used tiles
    for (int idx = tid; idx < lim; idx += 256) {
        int slot = idx >> 7, pl = idx & 127;
        int node = s_order[slot];
        float v = (node >= 0 && pl < rows) ? (float)m8[pl * NNODE + node] : 0.f;
        g_mTbf[(size_t)slot * PIXP + p0 + pl] = __float2half(v);
    }
}

// ---------------------------------------------------------------------------
// K_cvt_x: transpose x[C][PIX] -> xh [PIXP][C] (fp16)
// ---------------------------------------------------------------------------
__global__ void k_cvt_x(const float* __restrict__ x) {
    __shared__ float t[32][33];
    int p0 = blockIdx.x * 32, c0 = blockIdx.y * 32;
    int tx = threadIdx.x, ty = threadIdx.y;
#pragma unroll
    for (int i = 0; i < 4; i++) {
        int c = c0 + ty + i * 8, p = p0 + tx;
        t[ty + i * 8][tx] = (p < PIX) ? x[(size_t)c * PIX + p] : 0.f;
    }
    __syncthreads();
#pragma unroll
    for (int i = 0; i < 4; i++) {
        int p = p0 + ty + i * 8, c = c0 + tx;
        g_xh[(size_t)p * CIN + c] = __float2half(t[tx][ty + i * 8]);
    }
}

// K_cvt_w: transpose W1[C][R] -> [branch][R][C] fp16
__global__ void k_cvt_w(const float* __restrict__ Wp, const float* __restrict__ Wl,
                        const float* __restrict__ Wc) {
    __shared__ float t[32][33];
    const float* W = blockIdx.z == 0 ? Wp : (blockIdx.z == 1 ? Wl : Wc);
    int r0 = blockIdx.x * 32, c0 = blockIdx.y * 32;
    int tx = threadIdx.x, ty = threadIdx.y;
#pragma unroll
    for (int i = 0; i < 4; i++)
        t[ty + i * 8][tx] = W[(size_t)(c0 + ty + i * 8) * RDIM + r0 + tx];
    __syncthreads();
    size_t base = (size_t)blockIdx.z * RDIM * CIN;
#pragma unroll
    for (int i = 0; i < 4; i++) {
        int r = r0 + ty + i * 8, c = c0 + tx;
        g_w1[base + (size_t)r * CIN + c] = __float2half(t[tx][ty + i * 8]);
    }
}

// ---------------------------------------------------------------------------
// K2: layer-1 fp16 mma.sync, cp.async double-buffered, ldmatrix.
// Block 128p x 128r, 4 warps (2m x 2n), warp tile 64x64.
// ---------------------------------------------------------------------------
__global__ __launch_bounds__(128) void k_layer1_mma(
    const float* __restrict__ b1p, const float* __restrict__ b1l,
    const float* __restrict__ b1c)
{
    __shared__ __align__(16) fp16 sm[4 * 128 * LDK];   // 40960B: A0,A1,B0,B1
    fp16* Abuf[2] = { sm, sm + 128 * LDK };
    fp16* Bbuf[2] = { sm + 2 * 128 * LDK, sm + 3 * 128 * LDK };

    int branch = blockIdx.z;
    const float* bias = branch == 0 ? b1p : (branch == 1 ? b1l : b1c);
    size_t p0 = (size_t)blockIdx.x * 128;
    int r0 = blockIdx.y * 128;
    int tid = threadIdx.x;
    int warp = tid >> 5, lane = tid & 31;
    int gid = lane >> 2, tg = lane & 3;
    int wm = warp & 1, wn = warp >> 1;
    int fr = lane & 15, fo = (lane >> 4) * 8;

    float acc[4][8][4];
#pragma unroll
    for (int a = 0; a < 4; a++)
#pragma unroll
        for (int b = 0; b < 8; b++)
#pragma unroll
            for (int cte = 0; cte < 4; cte++) acc[a][b][cte] = 0.f;

    size_t wbase = (size_t)branch * RDIM * CIN;

    auto issue = [&](int buf, int c0) {
#pragma unroll
        for (int j = 0; j < 4; j++) {
            int idx = tid + j * 128;
            int row = idx >> 2, o = (idx & 3) * 8;
            CP16(s2u(&Abuf[buf][row * LDK + o]), &g_xh[(p0 + row) * CIN + c0 + o]);
            CP16(s2u(&Bbuf[buf][row * LDK + o]), &g_w1[wbase + (size_t)(r0 + row) * CIN + c0 + o]);
        }
        CPCOMMIT();
    };

    issue(0, 0);
    int buf = 0;
    for (int it = 0; it < 8; it++) {
        if (it < 7) issue(buf ^ 1, (it + 1) * 32);
        if (it < 7) CPWAIT1(); else CPWAIT0();
        __syncthreads();

        uint32_t uA = s2u(Abuf[buf]) + (uint32_t)(((wm * 64 + fr) * LDK + fo) * 2);
        uint32_t uB = s2u(Bbuf[buf]) + (uint32_t)(((wn * 64 + fr) * LDK + fo) * 2);
#pragma unroll
        for (int kk = 0; kk < 2; kk++) {
            uint32_t B0[8], B1[8];
#pragma unroll
            for (int pair = 0; pair < 4; pair++) {
                uint32_t t[4];
                ldsm4(t, uB + (uint32_t)((pair * 16 * LDK + kk * 16) * 2));
                B0[pair * 2] = t[0]; B0[pair * 2 + 1] = t[1];
                B1[pair * 2] = t[2]; B1[pair * 2 + 1] = t[3];
            }
#pragma unroll
            for (int mi = 0; mi < 4; mi++) {
                uint32_t a[4];
                ldsm4(a, uA + (uint32_t)((mi * 16 * LDK + kk * 16) * 2));
#pragma unroll
                for (int ni = 0; ni < 8; ni++)
                    mma16816(acc[mi][ni], a[0], a[1], a[2], a[3], B0[ni], B1[ni]);
            }
        }
        __syncthreads();
        buf ^= 1;
    }

    // Epilogue: bias + relu, fp16, transpose via smem, store H^T[r][p]
    fp16* sT = sm;   // pitch 136; 34816B <= 40960B
#pragma unroll
    for (int mi = 0; mi < 4; mi++) {
        int pr = wm * 64 + mi * 16 + gid;
#pragma unroll
        for (int ni = 0; ni < 8; ni++) {
            int j = wn * 64 + ni * 8 + tg * 2;
            float bb0 = bias[r0 + j], bb1 = bias[r0 + j + 1];
            sT[j * 136 + pr]           = __float2half(fmaxf(acc[mi][ni][0] + bb0, 0.f));
            sT[(j + 1) * 136 + pr]     = __float2half(fmaxf(acc[mi][ni][1] + bb1, 0.f));
            sT[j * 136 + pr + 8]       = __float2half(fmaxf(acc[mi][ni][2] + bb0, 0.f));
            sT[(j + 1) * 136 + pr + 8] = __float2half(fmaxf(acc[mi][ni][3] + bb1, 0.f));
        }
    }
    __syncthreads();
    size_t hbase = (size_t)branch * RDIM * PIXP;
    for (int idx = tid; idx < 128 * 16; idx += 128) {
        int rl = idx >> 4, ch = idx & 15;
        *(uint4*)&g_H[hbase + (size_t)(r0 + rl) * PIXP + p0 + ch * 8] =
            *(uint4*)&sT[rl * 136 + ch * 8];
    }
}

// ---------------------------------------------------------------------------
// K3: mask-GEMM fp16 mma.sync, cp.async double-buffered, ldmatrix, split-K.
// Block 128n x 128r, 4 warps (2m x 2n), warp tile 64x64.
// ---------------------------------------------------------------------------
__global__ __launch_bounds__(128) void k_maskgemm_mma() {
    int tileN = blockIdx.x;
    int lab = g_tileLabel[tileN];
    if (lab < 0) return;
    int r0 = blockIdx.y * 128;
    int ks = blockIdx.z;

    __shared__ __align__(16) fp16 sm[4 * 128 * LDK];
    fp16* Mbuf[2] = { sm, sm + 128 * LDK };
    fp16* Bbuf[2] = { sm + 2 * 128 * LDK, sm + 3 * 128 * LDK };
    __shared__ int nodes[NTILE];

    int tid = threadIdx.x;
    nodes[tid] = g_order[tileN * NTILE + tid];

    int warp = tid >> 5, lane = tid & 31;
    int gid = lane >> 2, tg = lane & 3;
    int wm = warp & 1, wn = warp >> 1;
    int fr = lane & 15, fo = (lane >> 4) * 8;

    float acc[4][8][4];
#pragma unroll
    for (int a = 0; a < 4; a++)
#pragma unroll
        for (int b = 0; b < 8; b++)
#pragma unroll
            for (int cte = 0; cte < 4; cte++) acc[a][b][cte] = 0.f;

    const fp16* HT = g_H + (size_t)lab * RDIM * PIXP;
    const fp16* MT = g_mTbf + (size_t)tileN * NTILE * PIXP;
    int pbase = ks * PCHUNK;

    auto issue = [&](int buf, int pp) {
#pragma unroll
        for (int j = 0; j < 4; j++) {
            int idx = tid + j * 128;
            int row = idx >> 2, o = (idx & 3) * 8;
            CP16(s2u(&Mbuf[buf][row * LDK + o]), &MT[(size_t)row * PIXP + pbase + pp + o]);
            CP16(s2u(&Bbuf[buf][row * LDK + o]), &HT[(size_t)(r0 + row) * PIXP + pbase + pp + o]);
        }
        CPCOMMIT();
    };

    const int ITER = PCHUNK / 32;   // 125
    issue(0, 0);
    int buf = 0;
    for (int it = 0; it < ITER; it++) {
        if (it < ITER - 1) issue(buf ^ 1, (it + 1) * 32);
        if (it < ITER - 1) CPWAIT1(); else CPWAIT0();
        __syncthreads();

        uint32_t uM = s2u(Mbuf[buf]) + (uint32_t)(((wm * 64 + fr) * LDK + fo) * 2);
        uint32_t uB = s2u(Bbuf[buf]) + (uint32_t)(((wn * 64 + fr) * LDK + fo) * 2);
#pragma unroll
        for (int kk = 0; kk < 2; kk++) {
            uint32_t B0[8], B1[8];
#pragma unroll
            for (int pair = 0; pair < 4; pair++) {
                uint32_t t[4];
                ldsm4(t, uB + (uint32_t)((pair * 16 * LDK + kk * 16) * 2));
                B0[pair * 2] = t[0]; B0[pair * 2 + 1] = t[1];
                B1[pair * 2] = t[2]; B1[pair * 2 + 1] = t[3];
            }
#pragma unroll
            for (int mi = 0; mi < 4; mi++) {
                uint32_t a[4];
                ldsm4(a, uM + (uint32_t)((mi * 16 * LDK + kk * 16) * 2));
#pragma unroll
                for (int ni = 0; ni < 8; ni++)
                    mma16816(acc[mi][ni], a[0], a[1], a[2], a[3], B0[ni], B1[ni]);
            }
        }
        __syncthreads();
        buf ^= 1;
    }

#pragma unroll
    for (int mi = 0; mi < 4; mi++) {
        int nodeA = nodes[wm * 64 + mi * 16 + gid];
        int nodeB = nodes[wm * 64 + mi * 16 + gid + 8];
#pragma unroll
        for (int ni = 0; ni < 8; ni++) {
            int r = r0 + wn * 64 + ni * 8 + tg * 2;
            if (nodeA >= 0)
                *(float2*)&g_Spart[((size_t)ks * NNODE + nodeA) * RDIM + r] =
                    make_float2(acc[mi][ni][0], acc[mi][ni][1]);
            if (nodeB >= 0)
                *(float2*)&g_Spart[((size_t)ks * NNODE + nodeB) * RDIM + r] =
                    make_float2(acc[mi][ni][2], acc[mi][ni][3]);
        }
    }
}

// K4: ordered split-K reduce + divide by count
__global__ void k_reduce() {
    int n = blockIdx.x;
    int r = blockIdx.y * 256 + threadIdx.x;
    float s = 0.f;
#pragma unroll
    for (int ks = 0; ks < KS; ks++)
        s += g_Spart[((size_t)ks * NNODE + n) * RDIM + r];
    g_S[(size_t)n * RDIM + r] = s / (float)g_counts[n];
}

// K5: layer-2 on 300 rows (fp32 SIMT — tiny)
__global__ __launch_bounds__(256) void k_layer2(
    const float* __restrict__ W2p, const float* __restrict__ b2p,
    const float* __restrict__ W2l, const float* __restrict__ b2l,
    const float* __restrict__ W2c, const float* __restrict__ b2c,
    float* __restrict__ out)
{
    int t8 = blockIdx.x;
    int lab = g_tileLabel[t8 >> 4];
    if (lab < 0) return;

    __shared__ float s[8][RDIM];
    __shared__ int nodes[8];
    int tid = threadIdx.x;
    if (tid < 8) nodes[tid] = g_order[t8 * 8 + tid];
    __syncthreads();
    bool any = false;
    for (int nd = 0; nd < 8; nd++) any |= (nodes[nd] >= 0);
    if (!any) return;

    const float* W2 = lab == 0 ? W2p : (lab == 1 ? W2l : W2c);
    const float* b2 = lab == 0 ? b2p : (lab == 1 ? b2l : b2c);

    for (int nd = 0; nd < 8; nd++) {
        int node = nodes[nd];
        for (int q = tid; q < RDIM; q += 256)
            s[nd][q] = (node >= 0) ? g_S[(size_t)node * RDIM + q] : 0.f;
    }
    __syncthreads();

    int r = blockIdx.y * 256 + tid;
    float acc[8];
#pragma unroll
    for (int nd = 0; nd < 8; nd++) acc[nd] = 0.f;
#pragma unroll 4
    for (int q = 0; q < RDIM; q++) {
        float w = W2[(size_t)q * RDIM + r];
#pragma unroll
        for (int nd = 0; nd < 8; nd++) acc[nd] += s[nd][q] * w;
    }
    float bb = b2[r];
#pragma unroll
    for (int nd = 0; nd < 8; nd++) {
        int node = nodes[nd];
        if (node >= 0) out[(size_t)node * RDIM + r] = acc[nd] + bb;
    }
}

// ---------------------------------------------------------------------------
extern "C" void kernel_launch(void* const* d_in, const int* in_sizes, int n_in,
                              void* d_out, int out_size) {
    const float* x      = (const float*)d_in[0];
    const void*  masks  = d_in[1];
    const int*   labels = (const int*)d_in[2];
    const float* W1[3] = { (const float*)d_in[3], (const float*)d_in[7],  (const float*)d_in[11] };
    const float* b1[3] = { (const float*)d_in[4], (const float*)d_in[8],  (const float*)d_in[12] };
    const float* W2[3] = { (const float*)d_in[5], (const float*)d_in[9],  (const float*)d_in[13] };
    const float* b2[3] = { (const float*)d_in[6], (const float*)d_in[10], (const float*)d_in[14] };
    float* out = (float*)d_out;

    k_prep<<<1, 32>>>(labels, masks);
    k_maskfuse<<<(PIX + 127) / 128, 256>>>(masks);
    k_cvt_x<<<dim3(PIXP / 32, CIN / 32), dim3(32, 8)>>>(x);
    k_cvt_w<<<dim3(RDIM / 32, CIN / 32, 3), dim3(32, 8)>>>(W1[0], W1[1], W1[2]);
    k_layer1_mma<<<dim3(PIXP / 128, RDIM / 128, 3), 128>>>(b1[0], b1[1], b1[2]);
    k_maskgemm_mma<<<dim3(MAXT, RDIM / 128, KS), 128>>>();
    k_reduce<<<dim3(NNODE, RDIM / 256), 256>>>();
    k_layer2<<<dim3(NSLOT / 8, RDIM / 256), 256>>>(
        W2[0], b2[0], W2[1], b2[1], W2[2], b2[2], out);
}

// round 10
// speedup vs baseline: 1.0986x; 1.0986x over previous
#include <cuda_runtime.h>
#include <cuda_fp16.h>
#include <cstdint>

// Problem constants
#define PIX    40000
#define PIXP   40064        // 313 * 128
#define CIN    256
#define RDIM   1024
#define NNODE  300
#define NTILE  128          // nodes per mask-GEMM tile
#define MAXT   6
#define NSLOT  (MAXT * NTILE)   // 768
#define KS     10
#define PCHUNK (PIX / KS)   // 4000
#define LDK    40           // smem k-pitch (fp16): 80B rows, 16B aligned

typedef __half fp16;

// Scratch (device globals — no allocation allowed)
__device__ fp16  g_H[(size_t)3 * RDIM * PIXP];          // H^T per branch [r][p], 246MB
__device__ fp16  g_xh[(size_t)PIXP * CIN];              // x transposed, fp16
__device__ fp16  g_w1[(size_t)3 * RDIM * CIN];          // W1^T fp16 [branch][r][c]
__device__ fp16  g_mTbf[(size_t)NSLOT * PIXP];          // masks transposed [slot][p]
__device__ float g_Spart[(size_t)KS * NNODE * RDIM];
__device__ float g_S[(size_t)NNODE * RDIM];
__device__ int   g_counts[NNODE];
__device__ int   g_order[NSLOT];
__device__ int   g_tileLabel[MAXT];
__device__ int   g_maskMode;                            // 0=u8, 1=i32, 2=f32
__device__ int   g_usedSlots;

// ---------------------------------------------------------------------------
__device__ __forceinline__ void mma16816(float* c, uint32_t a0, uint32_t a1,
                                         uint32_t a2, uint32_t a3,
                                         uint32_t b0, uint32_t b1) {
    asm volatile(
        "mma.sync.aligned.m16n8k16.row.col.f32.f16.f16.f32 "
        "{%0,%1,%2,%3},{%4,%5,%6,%7},{%8,%9},{%0,%1,%2,%3};"
        : "+f"(c[0]), "+f"(c[1]), "+f"(c[2]), "+f"(c[3])
        : "r"(a0), "r"(a1), "r"(a2), "r"(a3), "r"(b0), "r"(b1));
}
__device__ __forceinline__ uint32_t s2u(const void* p) {
    return (uint32_t)__cvta_generic_to_shared(p);
}
__device__ __forceinline__ void ldsm4(uint32_t* r, uint32_t a) {
    asm volatile("ldmatrix.sync.aligned.m8n8.x4.shared.b16 {%0,%1,%2,%3},[%4];"
                 : "=r"(r[0]), "=r"(r[1]), "=r"(r[2]), "=r"(r[3]) : "r"(a));
}
#define CP16(dst, src) asm volatile("cp.async.cg.shared.global [%0],[%1],16;\n" :: "r"(dst), "l"(src))
#define CPCOMMIT() asm volatile("cp.async.commit_group;\n" ::)
#define CPWAIT1() asm volatile("cp.async.wait_group 1;\n" ::)
#define CPWAIT0() asm volatile("cp.async.wait_group 0;\n" ::)

// ---------------------------------------------------------------------------
// K0: detect mask dtype; bucket nodes by label into 128-padded tiles; zero counts.
// ---------------------------------------------------------------------------
__global__ void k_prep(const int* __restrict__ labels, const void* __restrict__ masks_raw) {
    if (threadIdx.x != 0) return;
    const unsigned int* w = (const unsigned int*)masks_raw;
    bool sawFloat = false, sawGT1 = false;
    for (int i = 0; i < 4096; i++) {
        unsigned int v = w[i];
        if (v == 0x3F800000u) sawFloat = true;
        else if (v > 1u) sawGT1 = true;
    }
    g_maskMode = sawFloat ? 2 : (sawGT1 ? 0 : 1);

    for (int i = 0; i < NNODE; i++) g_counts[i] = 0;
    int pos = 0, tile = 0;
    for (int lab = 0; lab < 3; lab++) {
        int start = pos;
        for (int n = 0; n < NNODE; n++)
            if (labels[n] == lab) g_order[pos++] = n;
        if (pos > start) {
            while ((pos - start) % NTILE) g_order[pos++] = -1;
            for (int t = start; t < pos; t += NTILE) g_tileLabel[tile++] = lab;
        }
    }
    g_usedSlots = pos;
    while (pos < NSLOT) g_order[pos++] = -1;
    for (; tile < MAXT; tile++) g_tileLabel[tile] = -1;
}

// ---------------------------------------------------------------------------
// K1 (fused): per 128-pixel block — raw masks -> smem, counts, transposed fp16.
// ---------------------------------------------------------------------------
__global__ __launch_bounds__(256) void k_maskfuse(const void* __restrict__ masks_raw) {
    __shared__ unsigned char m8[128 * NNODE];
    __shared__ int s_order[NSLOT];

    int tid = threadIdx.x;
    int p0 = blockIdx.x * 128;
    int rows = PIX - p0; if (rows > 128) rows = 128;
    int mode = g_maskMode;
    int used = g_usedSlots;

    for (int i = tid; i < NSLOT; i += 256) s_order[i] = g_order[i];

    int total = rows * NNODE;
    if (mode == 0) {
        const unsigned int* src = (const unsigned int*)masks_raw + (size_t)p0 * NNODE / 4;
        unsigned int* dst = (unsigned int*)m8;
        for (int i = tid; i < total / 4; i += 256) dst[i] = src[i];
        for (int i = total & ~3; i < total; i++) if (tid == 0) m8[i] = ((const unsigned char*)masks_raw)[(size_t)p0 * NNODE + i];
    } else if (mode == 1) {
        const int* src = (const int*)masks_raw + (size_t)p0 * NNODE;
        for (int i = tid; i < total; i += 256) m8[i] = (unsigned char)(src[i] != 0);
    } else {
        const float* src = (const float*)masks_raw + (size_t)p0 * NNODE;
        for (int i = tid; i < total; i += 256) m8[i] = (unsigned char)(src[i] != 0.0f);
    }
    __syncthreads();

    for (int n = tid; n < NNODE; n += 256) {
        int c = 0;
        for (int pl = 0; pl < rows; pl++) c += m8[pl * NNODE + n];
        atomicAdd(&g_counts[n], c);
    }

    int lim = ((used + NTILE - 1) / NTILE) * NTILE * 128;
    for (int idx = tid; idx < lim; idx += 256) {
        int slot = idx >> 7, pl = idx & 127;
        int node = s_order[slot];
        float v = (node >= 0 && pl < rows) ? (float)m8[pl * NNODE + node] : 0.f;
        g_mTbf[(size_t)slot * PIXP + p0 + pl] = __float2half(v);
    }
}

// ---------------------------------------------------------------------------
// K_cvt_x: transpose x[C][PIX] -> xh [PIXP][C] (fp16)
// ---------------------------------------------------------------------------
__global__ void k_cvt_x(const float* __restrict__ x) {
    __shared__ float t[32][33];
    int p0 = blockIdx.x * 32, c0 = blockIdx.y * 32;
    int tx = threadIdx.x, ty = threadIdx.y;
#pragma unroll
    for (int i = 0; i < 4; i++) {
        int c = c0 + ty + i * 8, p = p0 + tx;
        t[ty + i * 8][tx] = (p < PIX) ? x[(size_t)c * PIX + p] : 0.f;
    }
    __syncthreads();
#pragma unroll
    for (int i = 0; i < 4; i++) {
        int p = p0 + ty + i * 8, c = c0 + tx;
        g_xh[(size_t)p * CIN + c] = __float2half(t[tx][ty + i * 8]);
    }
}

// K_cvt_w: transpose W1[C][R] -> [branch][R][C] fp16
__global__ void k_cvt_w(const float* __restrict__ Wp, const float* __restrict__ Wl,
                        const float* __restrict__ Wc) {
    __shared__ float t[32][33];
    const float* W = blockIdx.z == 0 ? Wp : (blockIdx.z == 1 ? Wl : Wc);
    int r0 = blockIdx.x * 32, c0 = blockIdx.y * 32;
    int tx = threadIdx.x, ty = threadIdx.y;
#pragma unroll
    for (int i = 0; i < 4; i++)
        t[ty + i * 8][tx] = W[(size_t)(c0 + ty + i * 8) * RDIM + r0 + tx];
    __syncthreads();
    size_t base = (size_t)blockIdx.z * RDIM * CIN;
#pragma unroll
    for (int i = 0; i < 4; i++) {
        int r = r0 + ty + i * 8, c = c0 + tx;
        g_w1[base + (size_t)r * CIN + c] = __float2half(t[tx][ty + i * 8]);
    }
}

// ---------------------------------------------------------------------------
// K2: layer-1 fp16 mma.sync, cp.async double-buffered, ldmatrix.
// Block 128p x 128r, 8 warps (2m x 4n), warp tile 64x32.  2 CTAs/SM.
// ---------------------------------------------------------------------------
__global__ __launch_bounds__(256, 2) void k_layer1_mma(
    const float* __restrict__ b1p, const float* __restrict__ b1l,
    const float* __restrict__ b1c)
{
    __shared__ __align__(16) fp16 sm[4 * 128 * LDK];   // 40960B: A0,A1,B0,B1
    fp16* Abuf[2] = { sm, sm + 128 * LDK };
    fp16* Bbuf[2] = { sm + 2 * 128 * LDK, sm + 3 * 128 * LDK };

    int branch = blockIdx.z;
    const float* bias = branch == 0 ? b1p : (branch == 1 ? b1l : b1c);
    size_t p0 = (size_t)blockIdx.x * 128;
    int r0 = blockIdx.y * 128;
    int tid = threadIdx.x;
    int warp = tid >> 5, lane = tid & 31;
    int gid = lane >> 2, tg = lane & 3;
    int wm = warp & 1, wn = warp >> 1;
    int fr = lane & 15, fo = (lane >> 4) * 8;

    float acc[4][4][4];
#pragma unroll
    for (int a = 0; a < 4; a++)
#pragma unroll
        for (int b = 0; b < 4; b++)
#pragma unroll
            for (int cte = 0; cte < 4; cte++) acc[a][b][cte] = 0.f;

    size_t wbase = (size_t)branch * RDIM * CIN;

    auto issue = [&](int buf, int c0) {
#pragma unroll
        for (int j = 0; j < 2; j++) {
            int idx = tid + j * 256;
            int row = idx >> 2, o = (idx & 3) * 8;
            CP16(s2u(&Abuf[buf][row * LDK + o]), &g_xh[(p0 + row) * CIN + c0 + o]);
            CP16(s2u(&Bbuf[buf][row * LDK + o]), &g_w1[wbase + (size_t)(r0 + row) * CIN + c0 + o]);
        }
        CPCOMMIT();
    };

    issue(0, 0);
    int buf = 0;
    for (int it = 0; it < 8; it++) {
        if (it < 7) issue(buf ^ 1, (it + 1) * 32);
        if (it < 7) CPWAIT1(); else CPWAIT0();
        __syncthreads();

        uint32_t uA = s2u(Abuf[buf]) + (uint32_t)(((wm * 64 + fr) * LDK + fo) * 2);
        uint32_t uB = s2u(Bbuf[buf]) + (uint32_t)(((wn * 32 + fr) * LDK + fo) * 2);
#pragma unroll
        for (int kk = 0; kk < 2; kk++) {
            uint32_t B0[4], B1[4];
#pragma unroll
            for (int pair = 0; pair < 2; pair++) {
                uint32_t t[4];
                ldsm4(t, uB + (uint32_t)((pair * 16 * LDK + kk * 16) * 2));
                B0[pair * 2] = t[0]; B0[pair * 2 + 1] = t[1];
                B1[pair * 2] = t[2]; B1[pair * 2 + 1] = t[3];
            }
#pragma unroll
            for (int mi = 0; mi < 4; mi++) {
                uint32_t a[4];
                ldsm4(a, uA + (uint32_t)((mi * 16 * LDK + kk * 16) * 2));
#pragma unroll
                for (int ni = 0; ni < 4; ni++)
                    mma16816(acc[mi][ni], a[0], a[1], a[2], a[3], B0[ni], B1[ni]);
            }
        }
        __syncthreads();
        buf ^= 1;
    }

    // Epilogue: bias + relu, fp16, transpose via smem, store H^T[r][p]
    fp16* sT = sm;   // pitch 136; 34816B <= 40960B
#pragma unroll
    for (int mi = 0; mi < 4; mi++) {
        int pr = wm * 64 + mi * 16 + gid;
#pragma unroll
        for (int ni = 0; ni < 4; ni++) {
            int j = wn * 32 + ni * 8 + tg * 2;
            float bb0 = bias[r0 + j], bb1 = bias[r0 + j + 1];
            sT[j * 136 + pr]           = __float2half(fmaxf(acc[mi][ni][0] + bb0, 0.f));
            sT[(j + 1) * 136 + pr]     = __float2half(fmaxf(acc[mi][ni][1] + bb1, 0.f));
            sT[j * 136 + pr + 8]       = __float2half(fmaxf(acc[mi][ni][2] + bb0, 0.f));
            sT[(j + 1) * 136 + pr + 8] = __float2half(fmaxf(acc[mi][ni][3] + bb1, 0.f));
        }
    }
    __syncthreads();
    size_t hbase = (size_t)branch * RDIM * PIXP;
    for (int idx = tid; idx < 128 * 16; idx += 256) {
        int rl = idx >> 4, ch = idx & 15;
        *(uint4*)&g_H[hbase + (size_t)(r0 + rl) * PIXP + p0 + ch * 8] =
            *(uint4*)&sT[rl * 136 + ch * 8];
    }
}

// ---------------------------------------------------------------------------
// K3: mask-GEMM fp16 mma.sync, cp.async double-buffered, ldmatrix, split-K.
// Block 128n x 128r, 8 warps (2m x 4n), warp tile 64x32.  2 CTAs/SM.
// ---------------------------------------------------------------------------
__global__ __launch_bounds__(256, 2) void k_maskgemm_mma() {
    int tileN = blockIdx.x;
    int lab = g_tileLabel[tileN];
    if (lab < 0) return;
    int r0 = blockIdx.y * 128;
    int ks = blockIdx.z;

    __shared__ __align__(16) fp16 sm[4 * 128 * LDK];
    fp16* Mbuf[2] = { sm, sm + 128 * LDK };
    fp16* Bbuf[2] = { sm + 2 * 128 * LDK, sm + 3 * 128 * LDK };
    __shared__ int nodes[NTILE];

    int tid = threadIdx.x;
    if (tid < NTILE) nodes[tid] = g_order[tileN * NTILE + tid];

    int warp = tid >> 5, lane = tid & 31;
    int gid = lane >> 2, tg = lane & 3;
    int wm = warp & 1, wn = warp >> 1;
    int fr = lane & 15, fo = (lane >> 4) * 8;

    float acc[4][4][4];
#pragma unroll
    for (int a = 0; a < 4; a++)
#pragma unroll
        for (int b = 0; b < 4; b++)
#pragma unroll
            for (int cte = 0; cte < 4; cte++) acc[a][b][cte] = 0.f;

    const fp16* HT = g_H + (size_t)lab * RDIM * PIXP;
    const fp16* MT = g_mTbf + (size_t)tileN * NTILE * PIXP;
    int pbase = ks * PCHUNK;

    auto issue = [&](int buf, int pp) {
#pragma unroll
        for (int j = 0; j < 2; j++) {
            int idx = tid + j * 256;
            int row = idx >> 2, o = (idx & 3) * 8;
            CP16(s2u(&Mbuf[buf][row * LDK + o]), &MT[(size_t)row * PIXP + pbase + pp + o]);
            CP16(s2u(&Bbuf[buf][row * LDK + o]), &HT[(size_t)(r0 + row) * PIXP + pbase + pp + o]);
        }
        CPCOMMIT();
    };

    const int ITER = PCHUNK / 32;   // 125
    issue(0, 0);
    int buf = 0;
    for (int it = 0; it < ITER; it++) {
        if (it < ITER - 1) issue(buf ^ 1, (it + 1) * 32);
        if (it < ITER - 1) CPWAIT1(); else CPWAIT0();
        __syncthreads();

        uint32_t uM = s2u(Mbuf[buf]) + (uint32_t)(((wm * 64 + fr) * LDK + fo) * 2);
        uint32_t uB = s2u(Bbuf[buf]) + (uint32_t)(((wn * 32 + fr) * LDK + fo) * 2);
#pragma unroll
        for (int kk = 0; kk < 2; kk++) {
            uint32_t B0[4], B1[4];
#pragma unroll
            for (int pair = 0; pair < 2; pair++) {
                uint32_t t[4];
                ldsm4(t, uB + (uint32_t)((pair * 16 * LDK + kk * 16) * 2));
                B0[pair * 2] = t[0]; B0[pair * 2 + 1] = t[1];
                B1[pair * 2] = t[2]; B1[pair * 2 + 1] = t[3];
            }
#pragma unroll
            for (int mi = 0; mi < 4; mi++) {
                uint32_t a[4];
                ldsm4(a, uM + (uint32_t)((mi * 16 * LDK + kk * 16) * 2));
#pragma unroll
                for (int ni = 0; ni < 4; ni++)
                    mma16816(acc[mi][ni], a[0], a[1], a[2], a[3], B0[ni], B1[ni]);
            }
        }
        __syncthreads();
        buf ^= 1;
    }

#pragma unroll
    for (int mi = 0; mi < 4; mi++) {
        int nodeA = nodes[wm * 64 + mi * 16 + gid];
        int nodeB = nodes[wm * 64 + mi * 16 + gid + 8];
#pragma unroll
        for (int ni = 0; ni < 4; ni++) {
            int r = r0 + wn * 32 + ni * 8 + tg * 2;
            if (nodeA >= 0)
                *(float2*)&g_Spart[((size_t)ks * NNODE + nodeA) * RDIM + r] =
                    make_float2(acc[mi][ni][0], acc[mi][ni][1]);
            if (nodeB >= 0)
                *(float2*)&g_Spart[((size_t)ks * NNODE + nodeB) * RDIM + r] =
                    make_float2(acc[mi][ni][2], acc[mi][ni][3]);
        }
    }
}

// K4: ordered split-K reduce + divide by count
__global__ void k_reduce() {
    int n = blockIdx.x;
    int r = blockIdx.y * 256 + threadIdx.x;
    float s = 0.f;
#pragma unroll
    for (int ks = 0; ks < KS; ks++)
        s += g_Spart[((size_t)ks * NNODE + n) * RDIM + r];
    g_S[(size_t)n * RDIM + r] = s / (float)g_counts[n];
}

// K5: layer-2 on 300 rows (fp32 SIMT — tiny)
__global__ __launch_bounds__(256) void k_layer2(
    const float* __restrict__ W2p, const float* __restrict__ b2p,
    const float* __restrict__ W2l, const float* __restrict__ b2l,
    const float* __restrict__ W2c, const float* __restrict__ b2c,
    float* __restrict__ out)
{
    int t8 = blockIdx.x;
    int lab = g_tileLabel[t8 >> 4];
    if (lab < 0) return;

    __shared__ float s[8][RDIM];
    __shared__ int nodes[8];
    int tid = threadIdx.x;
    if (tid < 8) nodes[tid] = g_order[t8 * 8 + tid];
    __syncthreads();
    bool any = false;
    for (int nd = 0; nd < 8; nd++) any |= (nodes[nd] >= 0);
    if (!any) return;

    const float* W2 = lab == 0 ? W2p : (lab == 1 ? W2l : W2c);
    const float* b2 = lab == 0 ? b2p : (lab == 1 ? b2l : b2c);

    for (int nd = 0; nd < 8; nd++) {
        int node = nodes[nd];
        for (int q = tid; q < RDIM; q += 256)
            s[nd][q] = (node >= 0) ? g_S[(size_t)node * RDIM + q] : 0.f;
    }
    __syncthreads();

    int r = blockIdx.y * 256 + tid;
    float acc[8];
#pragma unroll
    for (int nd = 0; nd < 8; nd++) acc[nd] = 0.f;
#pragma unroll 4
    for (int q = 0; q < RDIM; q++) {
        float w = W2[(size_t)q * RDIM + r];
#pragma unroll
        for (int nd = 0; nd < 8; nd++) acc[nd] += s[nd][q] * w;
    }
    float bb = b2[r];
#pragma unroll
    for (int nd = 0; nd < 8; nd++) {
        int node = nodes[nd];
        if (node >= 0) out[(size_t)node * RDIM + r] = acc[nd] + bb;
    }
}

// ---------------------------------------------------------------------------
extern "C" void kernel_launch(void* const* d_in, const int* in_sizes, int n_in,
                              void* d_out, int out_size) {
    const float* x      = (const float*)d_in[0];
    const void*  masks  = d_in[1];
    const int*   labels = (const int*)d_in[2];
    const float* W1[3] = { (const float*)d_in[3], (const float*)d_in[7],  (const float*)d_in[11] };
    const float* b1[3] = { (const float*)d_in[4], (const float*)d_in[8],  (const float*)d_in[12] };
    const float* W2[3] = { (const float*)d_in[5], (const float*)d_in[9],  (const float*)d_in[13] };
    const float* b2[3] = { (const float*)d_in[6], (const float*)d_in[10], (const float*)d_in[14] };
    float* out = (float*)d_out;

    k_prep<<<1, 32>>>(labels, masks);
    k_maskfuse<<<(PIX + 127) / 128, 256>>>(masks);
    k_cvt_x<<<dim3(PIXP / 32, CIN / 32), dim3(32, 8)>>>(x);
    k_cvt_w<<<dim3(RDIM / 32, CIN / 32, 3), dim3(32, 8)>>>(W1[0], W1[1], W1[2]);
    k_layer1_mma<<<dim3(PIXP / 128, RDIM / 128, 3), 256>>>(b1[0], b1[1], b1[2]);
    k_maskgemm_mma<<<dim3(MAXT, RDIM / 128, KS), 256>>>();
    k_reduce<<<dim3(NNODE, RDIM / 256), 256>>>();
    k_layer2<<<dim3(NSLOT / 8, RDIM / 256), 256>>>(
        W2[0], b2[0], W2[1], b2[1], W2[2], b2[2], out);
}